// round 3
// baseline (speedup 1.0000x reference)
#include <cuda_runtime.h>
#include <math.h>

// ---------------------------------------------------------------------------
// Problem constants
// ---------------------------------------------------------------------------
#define N_EMBD 2048
#define NH     16
#define HD     128
#define TT     2048         // seq len
#define BB     2            // batch
#define MROWS  (BB * TT)    // 4096 flattened (b, t) rows
#define QKV_N  (3 * N_EMBD) // 6144

// ---------------------------------------------------------------------------
// Scratch (no cudaMalloc allowed -> static __device__ globals)
// ---------------------------------------------------------------------------
__device__ float g_qkv[(size_t)MROWS * QKV_N];   // 100.7 MB
__device__ float g_y[(size_t)MROWS * N_EMBD];    //  33.6 MB
__device__ float g_cos[TT * (HD / 2)];
__device__ float g_sin[TT * (HD / 2)];

// ---------------------------------------------------------------------------
// RoPE cos/sin table (double-precision generation for accuracy)
// ---------------------------------------------------------------------------
__global__ void rope_table_kernel() {
    int idx = blockIdx.x * blockDim.x + threadIdx.x;
    if (idx >= TT * 64) return;
    int t = idx >> 6;
    int i = idx & 63;
    double theta = pow(10000.0, -(double)i / 64.0);
    double ang = (double)t * theta;
    g_cos[idx] = (float)cos(ang);
    g_sin[idx] = (float)sin(ang);
}

// Apply RoPE in-place to the q and k sections of g_qkv.
// Pairs are (2i, 2i+1) within each head's 128 dims.
__global__ void rope_apply_kernel() {
    int idx = blockIdx.x * blockDim.x + threadIdx.x;
    if (idx >= MROWS * 2048) return;       // 2048 pairs per row (q: 1024, k: 1024)
    int row = idx >> 11;
    int p   = idx & 2047;
    int sec = p >> 10;                     // 0 = q, 1 = k
    int pp  = p & 1023;
    int h   = pp >> 6;
    int i   = pp & 63;
    int t   = row & (TT - 1);
    int col = sec * N_EMBD + h * HD + 2 * i;
    float c = g_cos[t * 64 + i];
    float s = g_sin[t * 64 + i];
    float2* ptr = (float2*)(g_qkv + (size_t)row * QKV_N + col);
    float2 v = *ptr;
    float x0 = v.x, x1 = v.y;
    v.x = x0 * c - x1 * s;
    v.y = x1 * c + x0 * s;
    *ptr = v;
}

// ---------------------------------------------------------------------------
// SGEMM: C[M,N] = A[M,K] @ B[K,N], all row-major, dims divisible by tile.
// 128x128 block, BK=16, 256 threads, 8x8 per-thread register tile.
// Per-thread columns are split (tx*4 and 64+tx*4) so smem float4 reads are
// phase-contiguous (conflict-free).
// ---------------------------------------------------------------------------
__global__ __launch_bounds__(256, 2) void sgemm_kernel(
    const float* __restrict__ A, const float* __restrict__ B,
    float* __restrict__ C, int M, int N, int K)
{
    __shared__ float As[16][132];   // transposed A tile, padded
    __shared__ float Bs[16][128];

    int tid = threadIdx.x;
    int tx = tid & 15, ty = tid >> 4;

    int aRow = tid >> 2;            // 0..63
    int aCol = (tid & 3) << 2;      // 0,4,8,12
    int bRow = tid >> 5;            // 0..7
    int bCol = (tid & 31) << 2;     // 0..124

    size_t aBase = (size_t)(blockIdx.y) * 128 * K;
    int nBase = blockIdx.x * 128;

    float acc[8][8];
#pragma unroll
    for (int i = 0; i < 8; i++)
#pragma unroll
        for (int j = 0; j < 8; j++) acc[i][j] = 0.0f;

    for (int k0 = 0; k0 < K; k0 += 16) {
#pragma unroll
        for (int r = 0; r < 2; r++) {
            int m = aRow + r * 64;
            float4 a = *(const float4*)(A + aBase + (size_t)m * K + k0 + aCol);
            As[aCol + 0][m] = a.x;
            As[aCol + 1][m] = a.y;
            As[aCol + 2][m] = a.z;
            As[aCol + 3][m] = a.w;
        }
#pragma unroll
        for (int r = 0; r < 2; r++) {
            int kk = bRow + r * 8;
            *(float4*)&Bs[kk][bCol] =
                *(const float4*)(B + (size_t)(k0 + kk) * N + nBase + bCol);
        }
        __syncthreads();

#pragma unroll
        for (int k = 0; k < 16; k++) {
            float ra[8], rb[8];
            *(float4*)&ra[0] = *(const float4*)&As[k][ty * 8];
            *(float4*)&ra[4] = *(const float4*)&As[k][ty * 8 + 4];
            *(float4*)&rb[0] = *(const float4*)&Bs[k][tx * 4];
            *(float4*)&rb[4] = *(const float4*)&Bs[k][64 + tx * 4];
#pragma unroll
            for (int i = 0; i < 8; i++)
#pragma unroll
                for (int j = 0; j < 8; j++)
                    acc[i][j] = fmaf(ra[i], rb[j], acc[i][j]);
        }
        __syncthreads();
    }

#pragma unroll
    for (int i = 0; i < 8; i++) {
        size_t row = (size_t)blockIdx.y * 128 + ty * 8 + i;
        float4 o0 = make_float4(acc[i][0], acc[i][1], acc[i][2], acc[i][3]);
        float4 o1 = make_float4(acc[i][4], acc[i][5], acc[i][6], acc[i][7]);
        *(float4*)(C + row * N + nBase + tx * 4) = o0;
        *(float4*)(C + row * N + nBase + 64 + tx * 4) = o1;
    }
}

// ---------------------------------------------------------------------------
// Flash attention (fp32, non-causal, online softmax).
// One CTA = one (b, h, 64-query tile). 256 threads as 16x16 grid:
//   thread (ty,tx): S rows ty*4+i, S cols tx*4+j; O cols {tx*4+j, 64+tx*4+j}.
// Smem: Qt[128][64] (Q transposed), Kt[128][64] (K transposed),
//       Vs[64][128], Ps[64][68] (padded, row-major probs).
// ---------------------------------------------------------------------------
#define FA_SMEM_FLOATS (128 * 64 + 128 * 64 + 64 * 128 + 64 * 68)
#define FA_SMEM_BYTES  (FA_SMEM_FLOATS * 4)

__global__ __launch_bounds__(256, 1) void flash_kernel(
    const float* __restrict__ qkv, float* __restrict__ y)
{
    extern __shared__ float sm[];
    float* Qt = sm;                   // [128][64]
    float* Kt = Qt + 128 * 64;        // [128][64]
    float* Vs = Kt + 128 * 64;        // [64][128]
    float* Ps = Vs + 64 * 128;        // [64][68]

    int tid = threadIdx.x;
    int tx = tid & 15, ty = tid >> 4;
    int b = blockIdx.z, h = blockIdx.y;
    int qbase = blockIdx.x * 64;

    const float* qp = qkv + (size_t)b * TT * QKV_N + h * HD;
    const float* kp = qp + N_EMBD;
    const float* vp = qp + 2 * N_EMBD;

    int lane32 = tid & 31;
    int rr = tid >> 5;
    int dcol = lane32 * 4;

    // Load Q tile transposed: Qt[d][m]
#pragma unroll
    for (int it = 0; it < 8; it++) {
        int m = rr + it * 8;
        float4 qv = *(const float4*)(qp + (size_t)(qbase + m) * QKV_N + dcol);
        Qt[(dcol + 0) * 64 + m] = qv.x;
        Qt[(dcol + 1) * 64 + m] = qv.y;
        Qt[(dcol + 2) * 64 + m] = qv.z;
        Qt[(dcol + 3) * 64 + m] = qv.w;
    }

    float O[4][8];
    float mrow[4], lrow[4];
#pragma unroll
    for (int i = 0; i < 4; i++) {
        mrow[i] = -INFINITY;
        lrow[i] = 0.0f;
#pragma unroll
        for (int j = 0; j < 8; j++) O[i][j] = 0.0f;
    }

    const float scale = 0.08838834764831845f;  // 1/sqrt(128)

    for (int n0 = 0; n0 < TT; n0 += 64) {
        __syncthreads();  // protect Kt/Vs/Ps from previous iteration's readers

        // Load K tile transposed + V tile
#pragma unroll
        for (int it = 0; it < 8; it++) {
            int n = rr + it * 8;
            float4 kv = *(const float4*)(kp + (size_t)(n0 + n) * QKV_N + dcol);
            Kt[(dcol + 0) * 64 + n] = kv.x;
            Kt[(dcol + 1) * 64 + n] = kv.y;
            Kt[(dcol + 2) * 64 + n] = kv.z;
            Kt[(dcol + 3) * 64 + n] = kv.w;
            float4 vv = *(const float4*)(vp + (size_t)(n0 + n) * QKV_N + dcol);
            *(float4*)(Vs + n * 128 + dcol) = vv;
        }
        __syncthreads();

        // S = Q @ K^T   (4x4 per thread)
        float S[4][4];
#pragma unroll
        for (int i = 0; i < 4; i++)
#pragma unroll
            for (int j = 0; j < 4; j++) S[i][j] = 0.0f;

#pragma unroll 4
        for (int d = 0; d < 128; d++) {
            float qa[4], kb[4];
            *(float4*)qa = *(const float4*)(Qt + d * 64 + ty * 4);
            *(float4*)kb = *(const float4*)(Kt + d * 64 + tx * 4);
#pragma unroll
            for (int i = 0; i < 4; i++)
#pragma unroll
                for (int j = 0; j < 4; j++)
                    S[i][j] = fmaf(qa[i], kb[j], S[i][j]);
        }

        // Online softmax per row (16 threads share a row -> half-warp shfl)
#pragma unroll
        for (int i = 0; i < 4; i++) {
#pragma unroll
            for (int j = 0; j < 4; j++) S[i][j] *= scale;
            float mx = fmaxf(fmaxf(S[i][0], S[i][1]), fmaxf(S[i][2], S[i][3]));
#pragma unroll
            for (int sft = 1; sft < 16; sft <<= 1)
                mx = fmaxf(mx, __shfl_xor_sync(0xffffffffu, mx, sft));
            float mnew = fmaxf(mrow[i], mx);
            float alpha = __expf(mrow[i] - mnew);
            mrow[i] = mnew;
            float ps = 0.0f;
#pragma unroll
            for (int j = 0; j < 4; j++) {
                float p = __expf(S[i][j] - mnew);
                S[i][j] = p;
                ps += p;
            }
#pragma unroll
            for (int sft = 1; sft < 16; sft <<= 1)
                ps += __shfl_xor_sync(0xffffffffu, ps, sft);
            lrow[i] = lrow[i] * alpha + ps;
#pragma unroll
            for (int j = 0; j < 8; j++) O[i][j] *= alpha;
        }

        // Write P tile (row-major, padded rows, float4 stores)
#pragma unroll
        for (int i = 0; i < 4; i++) {
            float4 pv = make_float4(S[i][0], S[i][1], S[i][2], S[i][3]);
            *(float4*)(Ps + (ty * 4 + i) * 68 + tx * 4) = pv;
        }
        __syncthreads();

        // O += P @ V   (4 rows x 8 cols per thread)
#pragma unroll 4
        for (int n = 0; n < 64; n++) {
            float va[4], vb[4];
            *(float4*)va = *(const float4*)(Vs + n * 128 + tx * 4);
            *(float4*)vb = *(const float4*)(Vs + n * 128 + 64 + tx * 4);
#pragma unroll
            for (int i = 0; i < 4; i++) {
                float p = Ps[(ty * 4 + i) * 68 + n];
#pragma unroll
                for (int j = 0; j < 4; j++) {
                    O[i][j]     = fmaf(p, va[j], O[i][j]);
                    O[i][4 + j] = fmaf(p, vb[j], O[i][4 + j]);
                }
            }
        }
    }

    // Epilogue: normalize and store to g_y (layout [b*T + t][h*128 + d])
#pragma unroll
    for (int i = 0; i < 4; i++) {
        float inv = 1.0f / lrow[i];
        size_t row = (size_t)b * TT + qbase + ty * 4 + i;
        float4 o0 = make_float4(O[i][0] * inv, O[i][1] * inv, O[i][2] * inv, O[i][3] * inv);
        float4 o1 = make_float4(O[i][4] * inv, O[i][5] * inv, O[i][6] * inv, O[i][7] * inv);
        *(float4*)(y + row * N_EMBD + h * HD + tx * 4) = o0;
        *(float4*)(y + row * N_EMBD + h * HD + 64 + tx * 4) = o1;
    }
}

// ---------------------------------------------------------------------------
// Launch
// ---------------------------------------------------------------------------
extern "C" void kernel_launch(void* const* d_in, const int* in_sizes, int n_in,
                              void* d_out, int out_size)
{
    const float* x      = (const float*)d_in[0];
    const float* w_attn = (const float*)d_in[1];
    const float* w_proj = (const float*)d_in[2];
    float* out = (float*)d_out;

    float* qkv = nullptr;
    float* y = nullptr;
    cudaGetSymbolAddress((void**)&qkv, g_qkv);
    cudaGetSymbolAddress((void**)&y, g_y);

    cudaFuncSetAttribute(flash_kernel,
                         cudaFuncAttributeMaxDynamicSharedMemorySize,
                         FA_SMEM_BYTES);

    // 1. RoPE cos/sin table
    rope_table_kernel<<<(TT * 64 + 255) / 256, 256>>>();

    // 2. QKV projection: g_qkv = x @ w_attn   [4096 x 6144 x 2048]
    sgemm_kernel<<<dim3(QKV_N / 128, MROWS / 128), 256>>>(
        x, w_attn, qkv, MROWS, QKV_N, N_EMBD);

    // 3. RoPE on q and k sections (in place)
    rope_apply_kernel<<<(MROWS * 2048 + 255) / 256, 256>>>();

    // 4. Flash attention -> g_y
    flash_kernel<<<dim3(TT / 64, NH, BB), 256, FA_SMEM_BYTES>>>(qkv, y);

    // 5. Output projection: out = g_y @ w_proj   [4096 x 2048 x 2048]
    sgemm_kernel<<<dim3(N_EMBD / 128, MROWS / 128), 256>>>(
        y, w_proj, out, MROWS, N_EMBD, N_EMBD);
}

// round 5
// speedup vs baseline: 1.3870x; 1.3870x over previous
#include <cuda_runtime.h>
#include <cuda_bf16.h>
#include <stdint.h>
#include <math.h>

// ---------------------------------------------------------------------------
// Problem constants
// ---------------------------------------------------------------------------
#define N_EMBD 2048
#define NH     16
#define HD     128
#define TT     2048         // seq len
#define BB     2            // batch
#define MROWS  (BB * TT)    // 4096 flattened (b, t) rows
#define QKV_N  (3 * N_EMBD) // 6144

// ---------------------------------------------------------------------------
// Scratch (no cudaMalloc allowed -> static __device__ globals)
// ---------------------------------------------------------------------------
__device__ float g_qkv[(size_t)MROWS * QKV_N];   // 100.7 MB
__device__ float g_y[(size_t)MROWS * N_EMBD];    //  33.6 MB
__device__ float g_cos[TT * (HD / 2)];
__device__ float g_sin[TT * (HD / 2)];
// bf16 hi/lo split operands (reused across both GEMMs)
__device__ __nv_bfloat16 g_Ah[(size_t)MROWS * N_EMBD];
__device__ __nv_bfloat16 g_Al[(size_t)MROWS * N_EMBD];
__device__ __nv_bfloat16 g_Bh[(size_t)QKV_N * N_EMBD];   // [N][K] transposed
__device__ __nv_bfloat16 g_Bl[(size_t)QKV_N * N_EMBD];

// ---------------------------------------------------------------------------
// Helpers (plain sm_103-legal PTX only: ldmatrix / mma.sync / cp.async)
// ---------------------------------------------------------------------------
__device__ __forceinline__ uint32_t smem_u32(const void* p) {
    uint32_t a;
    asm("{ .reg .u64 t; cvta.to.shared.u64 t, %1; cvt.u32.u64 %0, t; }"
        : "=r"(a) : "l"(p));
    return a;
}

__device__ __forceinline__ void ldsm_x4(uint32_t* r, uint32_t addr) {
    asm volatile("ldmatrix.sync.aligned.m8n8.x4.shared.b16 {%0,%1,%2,%3}, [%4];"
                 : "=r"(r[0]), "=r"(r[1]), "=r"(r[2]), "=r"(r[3]) : "r"(addr));
}

__device__ __forceinline__ void mma16816(float* c, const uint32_t* a,
                                         const uint32_t* b) {
    asm volatile(
        "mma.sync.aligned.m16n8k16.row.col.f32.bf16.bf16.f32 "
        "{%0,%1,%2,%3}, {%4,%5,%6,%7}, {%8,%9}, {%0,%1,%2,%3};"
        : "+f"(c[0]), "+f"(c[1]), "+f"(c[2]), "+f"(c[3])
        : "r"(a[0]), "r"(a[1]), "r"(a[2]), "r"(a[3]), "r"(b[0]), "r"(b[1]));
}

#define CP_ASYNC16(dst, src) \
    asm volatile("cp.async.cg.shared.global [%0], [%1], 16;" \
                 :: "r"(dst), "l"(src) : "memory")
#define CP_COMMIT() asm volatile("cp.async.commit_group;" ::: "memory")
#define CP_WAIT1()  asm volatile("cp.async.wait_group 1;" ::: "memory")

__device__ __forceinline__ void split2(float x, __nv_bfloat16& h, __nv_bfloat16& l) {
    h = __float2bfloat16(x);
    l = __float2bfloat16(x - __bfloat162float(h));
}

// ---------------------------------------------------------------------------
// Convert kernels: fp32 -> bf16 hi/lo (same layout), and transposed variant
// ---------------------------------------------------------------------------
__global__ void conv_rm_kernel(const float* __restrict__ in,
                               __nv_bfloat16* __restrict__ oh,
                               __nv_bfloat16* __restrict__ ol, int n4) {
    int idx = blockIdx.x * blockDim.x + threadIdx.x;
    if (idx >= n4) return;
    float4 v = ((const float4*)in)[idx];
    __nv_bfloat16 h0, h1, h2, h3, l0, l1, l2, l3;
    split2(v.x, h0, l0); split2(v.y, h1, l1);
    split2(v.z, h2, l2); split2(v.w, h3, l3);
    ((__nv_bfloat162*)oh)[idx * 2]     = __halves2bfloat162(h0, h1);
    ((__nv_bfloat162*)oh)[idx * 2 + 1] = __halves2bfloat162(h2, h3);
    ((__nv_bfloat162*)ol)[idx * 2]     = __halves2bfloat162(l0, l1);
    ((__nv_bfloat162*)ol)[idx * 2 + 1] = __halves2bfloat162(l2, l3);
}

// B[K][N] fp32 row-major -> BT[N][K] bf16 hi/lo
__global__ void conv_tr_kernel(const float* __restrict__ B,
                               __nv_bfloat16* __restrict__ bh,
                               __nv_bfloat16* __restrict__ bl, int K, int N) {
    __shared__ float tile[32][33];
    int n0 = blockIdx.x * 32, k0 = blockIdx.y * 32;
    int tx = threadIdx.x, ty = threadIdx.y;
#pragma unroll
    for (int i = 0; i < 4; i++)
        tile[ty + i * 8][tx] = B[(size_t)(k0 + ty + i * 8) * N + n0 + tx];
    __syncthreads();
#pragma unroll
    for (int i = 0; i < 4; i++) {
        int n = ty + i * 8;
        float v = tile[tx][n];
        __nv_bfloat16 h, l;
        split2(v, h, l);
        size_t o = (size_t)(n0 + n) * K + k0 + tx;
        bh[o] = h;
        bl[o] = l;
    }
}

// ---------------------------------------------------------------------------
// RoPE
// ---------------------------------------------------------------------------
__global__ void rope_table_kernel() {
    int idx = blockIdx.x * blockDim.x + threadIdx.x;
    if (idx >= TT * 64) return;
    int t = idx >> 6;
    int i = idx & 63;
    double theta = pow(10000.0, -(double)i / 64.0);
    double ang = (double)t * theta;
    g_cos[idx] = (float)cos(ang);
    g_sin[idx] = (float)sin(ang);
}

__global__ void rope_apply_kernel() {
    int idx = blockIdx.x * blockDim.x + threadIdx.x;
    if (idx >= MROWS * 2048) return;
    int row = idx >> 11;
    int p   = idx & 2047;
    int sec = p >> 10;
    int pp  = p & 1023;
    int h   = pp >> 6;
    int i   = pp & 63;
    int t   = row & (TT - 1);
    int col = sec * N_EMBD + h * HD + 2 * i;
    float c = g_cos[t * 64 + i];
    float s = g_sin[t * 64 + i];
    float2* ptr = (float2*)(g_qkv + (size_t)row * QKV_N + col);
    float2 v = *ptr;
    float x0 = v.x, x1 = v.y;
    v.x = x0 * c - x1 * s;
    v.y = x1 * c + x0 * s;
    *ptr = v;
}

// ---------------------------------------------------------------------------
// Tensor-core GEMM via mma.sync (HMMA fallback path, legal on plain sm_103).
// C[M,N] = A[M,K] @ B^T with A=[M][K] bf16 hi/lo, B=[N][K] bf16 hi/lo.
// 3-term split accumulation in fp32 registers.
// CTA tile 128x128, BK=32, 8 warps (2 x 4), warp tile 64x32.
// Smem rows padded to 40 bf16 (80 B) -> ldmatrix phases bank-conflict-free.
// cp.async double buffering.
// ---------------------------------------------------------------------------
#define BM 128
#define BN 128
#define BK 32
#define PADB 80                       // padded row stride in bytes (40 bf16)
#define MAT_BYTES (128 * PADB)        // 10240 per matrix per stage
#define STG_BYTES (4 * MAT_BYTES)     // 40960 per stage
#define GEMM_SMEM (2 * STG_BYTES)     // 81920

__global__ __launch_bounds__(256, 1) void gemm_mma_kernel(
    const __nv_bfloat16* __restrict__ Ah, const __nv_bfloat16* __restrict__ Al,
    const __nv_bfloat16* __restrict__ Bh, const __nv_bfloat16* __restrict__ Bl,
    float* __restrict__ C, int M, int N, int K)
{
    extern __shared__ char smc[];
    const uint32_t sbase = smem_u32(smc);
    const int tid = threadIdx.x;
    const int lane = tid & 31;
    const int wid = tid >> 5;
    const int wm = wid & 1;           // 2 warps in M
    const int wn = wid >> 1;          // 4 warps in N
    const int mBase = blockIdx.y * BM;
    const int nBase = blockIdx.x * BN;
    const int nch = K / BK;

    const int ldRow = tid >> 2;       // 0..63
    const int ldCh  = tid & 3;        // 16B chunk within 64B row

    float acc[4][4][4];
#pragma unroll
    for (int i = 0; i < 4; i++)
#pragma unroll
        for (int j = 0; j < 4; j++)
#pragma unroll
            for (int r = 0; r < 4; r++) acc[i][j][r] = 0.0f;

    // --- stage loader (cp.async, 8 x 16B per thread) ---
    auto issue_stage = [&](int c, int buf) {
        const uint32_t st = sbase + buf * STG_BYTES;
        const int kOff = c * BK;
#pragma unroll
        for (int i = 0; i < 8; i++) {
            const int mat = i >> 1;                 // 0:Ah 1:Al 2:Bh 3:Bl
            const int row = (i & 1) * 64 + ldRow;
            const __nv_bfloat16* g;
            if (mat == 0)      g = Ah + (size_t)(mBase + row) * K + kOff;
            else if (mat == 1) g = Al + (size_t)(mBase + row) * K + kOff;
            else if (mat == 2) g = Bh + (size_t)(nBase + row) * K + kOff;
            else               g = Bl + (size_t)(nBase + row) * K + kOff;
            uint32_t dst = st + mat * MAT_BYTES + row * PADB + ldCh * 16;
            CP_ASYNC16(dst, g + ldCh * 8);
        }
    };

    issue_stage(0, 0);
    CP_COMMIT();

    // ldmatrix per-lane offsets
    const int arow = (lane & 7) + ((lane >> 3) & 1) * 8;   // A row-in-frag
    const int akc8 = (lane >> 4) * 8;                      // A k-offset
    const int brow = (lane & 7) + ((lane >> 4) & 1) * 8;   // B n-in-frag
    const int bkc8 = ((lane >> 3) & 1) * 8;                // B k-offset

    for (int c = 0; c < nch; c++) {
        const int buf = c & 1;
        if (c + 1 < nch) issue_stage(c + 1, (c + 1) & 1);
        CP_COMMIT();
        CP_WAIT1();
        __syncthreads();

        const uint32_t st = sbase + buf * STG_BYTES;
        const uint32_t ahB = st;
        const uint32_t alB = st + MAT_BYTES;
        const uint32_t bhB = st + 2 * MAT_BYTES;
        const uint32_t blB = st + 3 * MAT_BYTES;

#pragma unroll
        for (int s = 0; s < 2; s++) {
            const int kofs = s * 16;
            uint32_t ah[4][4], al[4][4];
#pragma unroll
            for (int fm = 0; fm < 4; fm++) {
                const uint32_t off =
                    (uint32_t)((wm * 64 + fm * 16 + arow) * PADB +
                               (kofs + akc8) * 2);
                ldsm_x4(ah[fm], ahB + off);
                ldsm_x4(al[fm], alB + off);
            }
            uint32_t bh[2][4], bl[2][4];
#pragma unroll
            for (int bi = 0; bi < 2; bi++) {
                const uint32_t off =
                    (uint32_t)((wn * 32 + bi * 16 + brow) * PADB +
                               (kofs + bkc8) * 2);
                ldsm_x4(bh[bi], bhB + off);
                ldsm_x4(bl[bi], blB + off);
            }
#pragma unroll
            for (int fm = 0; fm < 4; fm++) {
#pragma unroll
                for (int fn = 0; fn < 4; fn++) {
                    const uint32_t* ph = &bh[fn >> 1][(fn & 1) * 2];
                    const uint32_t* pl = &bl[fn >> 1][(fn & 1) * 2];
                    mma16816(acc[fm][fn], ah[fm], ph);   // hi * hi
                    mma16816(acc[fm][fn], ah[fm], pl);   // hi * lo
                    mma16816(acc[fm][fn], al[fm], ph);   // lo * hi
                }
            }
        }
        __syncthreads();
    }

    // Epilogue: direct float2 stores
    const int r0 = lane >> 2;
    const int c0 = (lane & 3) * 2;
#pragma unroll
    for (int fm = 0; fm < 4; fm++) {
#pragma unroll
        for (int fn = 0; fn < 4; fn++) {
            const size_t row = (size_t)(mBase + wm * 64 + fm * 16 + r0);
            const int col = nBase + wn * 32 + fn * 8 + c0;
            *(float2*)(C + row * N + col) =
                make_float2(acc[fm][fn][0], acc[fm][fn][1]);
            *(float2*)(C + (row + 8) * N + col) =
                make_float2(acc[fm][fn][2], acc[fm][fn][3]);
        }
    }
}

// ---------------------------------------------------------------------------
// Flash attention (fp32, non-causal, online softmax) — unchanged
// ---------------------------------------------------------------------------
#define FA_SMEM_FLOATS (128 * 64 + 128 * 64 + 64 * 128 + 64 * 68)
#define FA_SMEM_BYTES  (FA_SMEM_FLOATS * 4)

__global__ __launch_bounds__(256, 1) void flash_kernel(
    const float* __restrict__ qkv, float* __restrict__ y)
{
    extern __shared__ float smf[];
    float* Qt = smf;
    float* Kt = Qt + 128 * 64;
    float* Vs = Kt + 128 * 64;
    float* Ps = Vs + 64 * 128;

    int tid = threadIdx.x;
    int tx = tid & 15, ty = tid >> 4;
    int b = blockIdx.z, h = blockIdx.y;
    int qbase = blockIdx.x * 64;

    const float* qp = qkv + (size_t)b * TT * QKV_N + h * HD;
    const float* kp = qp + N_EMBD;
    const float* vp = qp + 2 * N_EMBD;

    int lane32 = tid & 31;
    int rr = tid >> 5;
    int dcol = lane32 * 4;

#pragma unroll
    for (int it = 0; it < 8; it++) {
        int m = rr + it * 8;
        float4 qv = *(const float4*)(qp + (size_t)(qbase + m) * QKV_N + dcol);
        Qt[(dcol + 0) * 64 + m] = qv.x;
        Qt[(dcol + 1) * 64 + m] = qv.y;
        Qt[(dcol + 2) * 64 + m] = qv.z;
        Qt[(dcol + 3) * 64 + m] = qv.w;
    }

    float O[4][8];
    float mrow[4], lrow[4];
#pragma unroll
    for (int i = 0; i < 4; i++) {
        mrow[i] = -INFINITY;
        lrow[i] = 0.0f;
#pragma unroll
        for (int j = 0; j < 8; j++) O[i][j] = 0.0f;
    }

    const float scale = 0.08838834764831845f;

    for (int n0 = 0; n0 < TT; n0 += 64) {
        __syncthreads();
#pragma unroll
        for (int it = 0; it < 8; it++) {
            int n = rr + it * 8;
            float4 kv = *(const float4*)(kp + (size_t)(n0 + n) * QKV_N + dcol);
            Kt[(dcol + 0) * 64 + n] = kv.x;
            Kt[(dcol + 1) * 64 + n] = kv.y;
            Kt[(dcol + 2) * 64 + n] = kv.z;
            Kt[(dcol + 3) * 64 + n] = kv.w;
            float4 vv = *(const float4*)(vp + (size_t)(n0 + n) * QKV_N + dcol);
            *(float4*)(Vs + n * 128 + dcol) = vv;
        }
        __syncthreads();

        float S[4][4];
#pragma unroll
        for (int i = 0; i < 4; i++)
#pragma unroll
            for (int j = 0; j < 4; j++) S[i][j] = 0.0f;

#pragma unroll 4
        for (int d = 0; d < 128; d++) {
            float qa[4], kb[4];
            *(float4*)qa = *(const float4*)(Qt + d * 64 + ty * 4);
            *(float4*)kb = *(const float4*)(Kt + d * 64 + tx * 4);
#pragma unroll
            for (int i = 0; i < 4; i++)
#pragma unroll
                for (int j = 0; j < 4; j++)
                    S[i][j] = fmaf(qa[i], kb[j], S[i][j]);
        }

#pragma unroll
        for (int i = 0; i < 4; i++) {
#pragma unroll
            for (int j = 0; j < 4; j++) S[i][j] *= scale;
            float mx = fmaxf(fmaxf(S[i][0], S[i][1]), fmaxf(S[i][2], S[i][3]));
#pragma unroll
            for (int sft = 1; sft < 16; sft <<= 1)
                mx = fmaxf(mx, __shfl_xor_sync(0xffffffffu, mx, sft));
            float mnew = fmaxf(mrow[i], mx);
            float alpha = __expf(mrow[i] - mnew);
            mrow[i] = mnew;
            float ps = 0.0f;
#pragma unroll
            for (int j = 0; j < 4; j++) {
                float p = __expf(S[i][j] - mnew);
                S[i][j] = p;
                ps += p;
            }
#pragma unroll
            for (int sft = 1; sft < 16; sft <<= 1)
                ps += __shfl_xor_sync(0xffffffffu, ps, sft);
            lrow[i] = lrow[i] * alpha + ps;
#pragma unroll
            for (int j = 0; j < 8; j++) O[i][j] *= alpha;
        }

#pragma unroll
        for (int i = 0; i < 4; i++) {
            float4 pv = make_float4(S[i][0], S[i][1], S[i][2], S[i][3]);
            *(float4*)(Ps + (ty * 4 + i) * 68 + tx * 4) = pv;
        }
        __syncthreads();

#pragma unroll 4
        for (int n = 0; n < 64; n++) {
            float va[4], vb[4];
            *(float4*)va = *(const float4*)(Vs + n * 128 + tx * 4);
            *(float4*)vb = *(const float4*)(Vs + n * 128 + 64 + tx * 4);
#pragma unroll
            for (int i = 0; i < 4; i++) {
                float p = Ps[(ty * 4 + i) * 68 + n];
#pragma unroll
                for (int j = 0; j < 4; j++) {
                    O[i][j]     = fmaf(p, va[j], O[i][j]);
                    O[i][4 + j] = fmaf(p, vb[j], O[i][4 + j]);
                }
            }
        }
    }

#pragma unroll
    for (int i = 0; i < 4; i++) {
        float inv = 1.0f / lrow[i];
        size_t row = (size_t)b * TT + qbase + ty * 4 + i;
        float4 o0 = make_float4(O[i][0] * inv, O[i][1] * inv, O[i][2] * inv, O[i][3] * inv);
        float4 o1 = make_float4(O[i][4] * inv, O[i][5] * inv, O[i][6] * inv, O[i][7] * inv);
        *(float4*)(y + row * N_EMBD + h * HD + tx * 4) = o0;
        *(float4*)(y + row * N_EMBD + h * HD + 64 + tx * 4) = o1;
    }
}

// ---------------------------------------------------------------------------
// Launch
// ---------------------------------------------------------------------------
extern "C" void kernel_launch(void* const* d_in, const int* in_sizes, int n_in,
                              void* d_out, int out_size)
{
    const float* x      = (const float*)d_in[0];
    const float* w_attn = (const float*)d_in[1];
    const float* w_proj = (const float*)d_in[2];
    float* out = (float*)d_out;

    float *qkv = nullptr, *y = nullptr;
    __nv_bfloat16 *Ah = nullptr, *Al = nullptr, *Bh = nullptr, *Bl = nullptr;
    cudaGetSymbolAddress((void**)&qkv, g_qkv);
    cudaGetSymbolAddress((void**)&y, g_y);
    cudaGetSymbolAddress((void**)&Ah, g_Ah);
    cudaGetSymbolAddress((void**)&Al, g_Al);
    cudaGetSymbolAddress((void**)&Bh, g_Bh);
    cudaGetSymbolAddress((void**)&Bl, g_Bl);

    cudaFuncSetAttribute(flash_kernel,
                         cudaFuncAttributeMaxDynamicSharedMemorySize, FA_SMEM_BYTES);
    cudaFuncSetAttribute(gemm_mma_kernel,
                         cudaFuncAttributeMaxDynamicSharedMemorySize, GEMM_SMEM);

    const int n4 = MROWS * N_EMBD / 4;

    // 1. RoPE table
    rope_table_kernel<<<(TT * 64 + 255) / 256, 256>>>();

    // 2. Split-convert x and w_attn (transposed to [N][K])
    conv_rm_kernel<<<(n4 + 255) / 256, 256>>>(x, Ah, Al, n4);
    conv_tr_kernel<<<dim3(QKV_N / 32, N_EMBD / 32), dim3(32, 8)>>>(
        w_attn, Bh, Bl, N_EMBD, QKV_N);

    // 3. QKV projection on tensor cores: g_qkv = x @ w_attn
    gemm_mma_kernel<<<dim3(QKV_N / BN, MROWS / BM), 256, GEMM_SMEM>>>(
        Ah, Al, Bh, Bl, qkv, MROWS, QKV_N, N_EMBD);

    // 4. RoPE on q, k
    rope_apply_kernel<<<(MROWS * 2048 + 255) / 256, 256>>>();

    // 5. Flash attention -> g_y
    flash_kernel<<<dim3(TT / 64, NH, BB), 256, FA_SMEM_BYTES>>>(qkv, y);

    // 6. Split-convert y and w_proj
    conv_rm_kernel<<<(n4 + 255) / 256, 256>>>(y, Ah, Al, n4);
    conv_tr_kernel<<<dim3(N_EMBD / 32, N_EMBD / 32), dim3(32, 8)>>>(
        w_proj, Bh, Bl, N_EMBD, N_EMBD);

    // 7. Output projection on tensor cores
    gemm_mma_kernel<<<dim3(N_EMBD / BN, MROWS / BM), 256, GEMM_SMEM>>>(
        Ah, Al, Bh, Bl, out, MROWS, N_EMBD, N_EMBD);
}

// round 6
// speedup vs baseline: 2.8109x; 2.0267x over previous
#include <cuda_runtime.h>
#include <cuda_bf16.h>
#include <stdint.h>
#include <math.h>

// ---------------------------------------------------------------------------
// Problem constants
// ---------------------------------------------------------------------------
#define N_EMBD 2048
#define NH     16
#define HD     128
#define TT     2048         // seq len
#define BB     2            // batch
#define MROWS  (BB * TT)    // 4096 flattened (b, t) rows
#define QKV_N  (3 * N_EMBD) // 6144

// ---------------------------------------------------------------------------
// Scratch (no cudaMalloc allowed -> static __device__ globals)
// ---------------------------------------------------------------------------
__device__ float g_qkv[(size_t)MROWS * QKV_N];   // 100.7 MB
__device__ float g_y[(size_t)MROWS * N_EMBD];    //  33.6 MB
__device__ float g_cos[TT * (HD / 2)];
__device__ float g_sin[TT * (HD / 2)];
// bf16 hi/lo split operands (multi-purpose, reused across phases)
__device__ __nv_bfloat16 g_Ah[(size_t)MROWS * N_EMBD];   // x-split / q-split / y-split
__device__ __nv_bfloat16 g_Al[(size_t)MROWS * N_EMBD];
__device__ __nv_bfloat16 g_Bh[(size_t)QKV_N * N_EMBD];   // w_attn^T / k-split / w_proj^T
__device__ __nv_bfloat16 g_Bl[(size_t)QKV_N * N_EMBD];
__device__ __nv_bfloat16 g_Vth[(size_t)MROWS * N_EMBD];  // V^T per head [bh][d][t]
__device__ __nv_bfloat16 g_Vtl[(size_t)MROWS * N_EMBD];

// ---------------------------------------------------------------------------
// Helpers (plain sm_103-legal PTX only: ldmatrix / mma.sync / cp.async)
// ---------------------------------------------------------------------------
__device__ __forceinline__ uint32_t smem_u32(const void* p) {
    uint32_t a;
    asm("{ .reg .u64 t; cvta.to.shared.u64 t, %1; cvt.u32.u64 %0, t; }"
        : "=r"(a) : "l"(p));
    return a;
}

__device__ __forceinline__ void ldsm_x4(uint32_t* r, uint32_t addr) {
    asm volatile("ldmatrix.sync.aligned.m8n8.x4.shared.b16 {%0,%1,%2,%3}, [%4];"
                 : "=r"(r[0]), "=r"(r[1]), "=r"(r[2]), "=r"(r[3]) : "r"(addr));
}

__device__ __forceinline__ void mma16816(float* c, const uint32_t* a,
                                         const uint32_t* b) {
    asm volatile(
        "mma.sync.aligned.m16n8k16.row.col.f32.bf16.bf16.f32 "
        "{%0,%1,%2,%3}, {%4,%5,%6,%7}, {%8,%9}, {%0,%1,%2,%3};"
        : "+f"(c[0]), "+f"(c[1]), "+f"(c[2]), "+f"(c[3])
        : "r"(a[0]), "r"(a[1]), "r"(a[2]), "r"(a[3]), "r"(b[0]), "r"(b[1]));
}

#define CP_ASYNC16(dst, src) \
    asm volatile("cp.async.cg.shared.global [%0], [%1], 16;" \
                 :: "r"(dst), "l"(src) : "memory")
#define CP_COMMIT() asm volatile("cp.async.commit_group;" ::: "memory")
#define CP_WAIT1()  asm volatile("cp.async.wait_group 1;" ::: "memory")

__device__ __forceinline__ void split2(float x, __nv_bfloat16& h, __nv_bfloat16& l) {
    h = __float2bfloat16(x);
    l = __float2bfloat16(x - __bfloat162float(h));
}

// pack two floats into bf16x2 hi + residual bf16x2 lo
__device__ __forceinline__ void pack_hl(float x, float y, uint32_t& h, uint32_t& l) {
    __nv_bfloat162 hh = __floats2bfloat162_rn(x, y);
    float rx = x - __bfloat162float(hh.x);
    float ry = y - __bfloat162float(hh.y);
    __nv_bfloat162 ll = __floats2bfloat162_rn(rx, ry);
    h = *(uint32_t*)&hh;
    l = *(uint32_t*)&ll;
}

// ---------------------------------------------------------------------------
// Convert kernels
// ---------------------------------------------------------------------------
__global__ void conv_rm_kernel(const float* __restrict__ in,
                               __nv_bfloat16* __restrict__ oh,
                               __nv_bfloat16* __restrict__ ol, int n4) {
    int idx = blockIdx.x * blockDim.x + threadIdx.x;
    if (idx >= n4) return;
    float4 v = ((const float4*)in)[idx];
    __nv_bfloat16 h0, h1, h2, h3, l0, l1, l2, l3;
    split2(v.x, h0, l0); split2(v.y, h1, l1);
    split2(v.z, h2, l2); split2(v.w, h3, l3);
    ((__nv_bfloat162*)oh)[idx * 2]     = __halves2bfloat162(h0, h1);
    ((__nv_bfloat162*)oh)[idx * 2 + 1] = __halves2bfloat162(h2, h3);
    ((__nv_bfloat162*)ol)[idx * 2]     = __halves2bfloat162(l0, l1);
    ((__nv_bfloat162*)ol)[idx * 2 + 1] = __halves2bfloat162(l2, l3);
}

// B[K][N] fp32 row-major -> BT[N][K] bf16 hi/lo
__global__ void conv_tr_kernel(const float* __restrict__ B,
                               __nv_bfloat16* __restrict__ bh,
                               __nv_bfloat16* __restrict__ bl, int K, int N) {
    __shared__ float tile[32][33];
    int n0 = blockIdx.x * 32, k0 = blockIdx.y * 32;
    int tx = threadIdx.x, ty = threadIdx.y;
#pragma unroll
    for (int i = 0; i < 4; i++)
        tile[ty + i * 8][tx] = B[(size_t)(k0 + ty + i * 8) * N + n0 + tx];
    __syncthreads();
#pragma unroll
    for (int i = 0; i < 4; i++) {
        int n = ty + i * 8;
        float v = tile[tx][n];
        __nv_bfloat16 h, l;
        split2(v, h, l);
        size_t o = (size_t)(n0 + n) * K + k0 + tx;
        bh[o] = h;
        bl[o] = l;
    }
}

// q or k section of g_qkv: apply RoPE + split to bf16 hi/lo [m][2048]
__global__ void conv_rope_kernel(const float* __restrict__ qkv, int secOff,
                                 __nv_bfloat16* __restrict__ oh,
                                 __nv_bfloat16* __restrict__ ol) {
    int idx = blockIdx.x * blockDim.x + threadIdx.x;
    if (idx >= MROWS * 512) return;
    int m = idx >> 9;
    int col = (idx & 511) * 4;
    int t = m & (TT - 1);
    int i0 = (col & 127) >> 1;
    float4 v = *(const float4*)(qkv + (size_t)m * QKV_N + secOff + col);
    float c0 = g_cos[t * 64 + i0],     s0 = g_sin[t * 64 + i0];
    float c1 = g_cos[t * 64 + i0 + 1], s1 = g_sin[t * 64 + i0 + 1];
    float r0 = v.x * c0 - v.y * s0;
    float r1 = v.y * c0 + v.x * s0;
    float r2 = v.z * c1 - v.w * s1;
    float r3 = v.w * c1 + v.z * s1;
    __nv_bfloat16 h0, h1, h2, h3, l0, l1, l2, l3;
    split2(r0, h0, l0); split2(r1, h1, l1);
    split2(r2, h2, l2); split2(r3, h3, l3);
    size_t o = (size_t)m * N_EMBD + col;
    *(__nv_bfloat162*)(oh + o)     = __halves2bfloat162(h0, h1);
    *(__nv_bfloat162*)(oh + o + 2) = __halves2bfloat162(h2, h3);
    *(__nv_bfloat162*)(ol + o)     = __halves2bfloat162(l0, l1);
    *(__nv_bfloat162*)(ol + o + 2) = __halves2bfloat162(l2, l3);
}

// V section of g_qkv -> per-head transposed bf16 hi/lo: vt[(bh*128+d)*2048 + t]
__global__ void conv_vt_kernel(const float* __restrict__ qkv,
                               __nv_bfloat16* __restrict__ vh,
                               __nv_bfloat16* __restrict__ vl) {
    __shared__ float tile[32][33];
    int bh = blockIdx.z;
    int b = bh >> 4, h = bh & 15;
    int t0 = blockIdx.x * 32, d0 = blockIdx.y * 32;
    int tx = threadIdx.x, ty = threadIdx.y;
#pragma unroll
    for (int i = 0; i < 4; i++)
        tile[ty + i * 8][tx] =
            qkv[(size_t)(b * TT + t0 + ty + i * 8) * QKV_N + 2 * N_EMBD + h * HD + d0 + tx];
    __syncthreads();
#pragma unroll
    for (int i = 0; i < 4; i++) {
        int d = ty + i * 8;
        float v = tile[tx][d];
        __nv_bfloat16 hh, ll;
        split2(v, hh, ll);
        size_t o = (size_t)(bh * HD + d0 + d) * TT + t0 + tx;
        vh[o] = hh;
        vl[o] = ll;
    }
}

// ---------------------------------------------------------------------------
// RoPE table
// ---------------------------------------------------------------------------
__global__ void rope_table_kernel() {
    int idx = blockIdx.x * blockDim.x + threadIdx.x;
    if (idx >= TT * 64) return;
    int t = idx >> 6;
    int i = idx & 63;
    double theta = pow(10000.0, -(double)i / 64.0);
    double ang = (double)t * theta;
    g_cos[idx] = (float)cos(ang);
    g_sin[idx] = (float)sin(ang);
}

// ---------------------------------------------------------------------------
// Tensor-core GEMM via mma.sync (unchanged from R4 — passed, tensor=52%)
// ---------------------------------------------------------------------------
#define BM 128
#define BN 128
#define BK 32
#define PADB 80
#define MAT_BYTES (128 * PADB)
#define STG_BYTES (4 * MAT_BYTES)
#define GEMM_SMEM (2 * STG_BYTES)

__global__ __launch_bounds__(256, 1) void gemm_mma_kernel(
    const __nv_bfloat16* __restrict__ Ah, const __nv_bfloat16* __restrict__ Al,
    const __nv_bfloat16* __restrict__ Bh, const __nv_bfloat16* __restrict__ Bl,
    float* __restrict__ C, int M, int N, int K)
{
    extern __shared__ char smc[];
    const uint32_t sbase = smem_u32(smc);
    const int tid = threadIdx.x;
    const int lane = tid & 31;
    const int wid = tid >> 5;
    const int wm = wid & 1;
    const int wn = wid >> 1;
    const int mBase = blockIdx.y * BM;
    const int nBase = blockIdx.x * BN;
    const int nch = K / BK;

    const int ldRow = tid >> 2;
    const int ldCh  = tid & 3;

    float acc[4][4][4];
#pragma unroll
    for (int i = 0; i < 4; i++)
#pragma unroll
        for (int j = 0; j < 4; j++)
#pragma unroll
            for (int r = 0; r < 4; r++) acc[i][j][r] = 0.0f;

    auto issue_stage = [&](int c, int buf) {
        const uint32_t st = sbase + buf * STG_BYTES;
        const int kOff = c * BK;
#pragma unroll
        for (int i = 0; i < 8; i++) {
            const int mat = i >> 1;
            const int row = (i & 1) * 64 + ldRow;
            const __nv_bfloat16* g;
            if (mat == 0)      g = Ah + (size_t)(mBase + row) * K + kOff;
            else if (mat == 1) g = Al + (size_t)(mBase + row) * K + kOff;
            else if (mat == 2) g = Bh + (size_t)(nBase + row) * K + kOff;
            else               g = Bl + (size_t)(nBase + row) * K + kOff;
            uint32_t dst = st + mat * MAT_BYTES + row * PADB + ldCh * 16;
            CP_ASYNC16(dst, g + ldCh * 8);
        }
    };

    issue_stage(0, 0);
    CP_COMMIT();

    const int arow = (lane & 7) + ((lane >> 3) & 1) * 8;
    const int akc8 = (lane >> 4) * 8;
    const int brow = (lane & 7) + ((lane >> 4) & 1) * 8;
    const int bkc8 = ((lane >> 3) & 1) * 8;

    for (int c = 0; c < nch; c++) {
        const int buf = c & 1;
        if (c + 1 < nch) issue_stage(c + 1, (c + 1) & 1);
        CP_COMMIT();
        CP_WAIT1();
        __syncthreads();

        const uint32_t st = sbase + buf * STG_BYTES;
        const uint32_t ahB = st;
        const uint32_t alB = st + MAT_BYTES;
        const uint32_t bhB = st + 2 * MAT_BYTES;
        const uint32_t blB = st + 3 * MAT_BYTES;

#pragma unroll
        for (int s = 0; s < 2; s++) {
            const int kofs = s * 16;
            uint32_t ah[4][4], al[4][4];
#pragma unroll
            for (int fm = 0; fm < 4; fm++) {
                const uint32_t off =
                    (uint32_t)((wm * 64 + fm * 16 + arow) * PADB +
                               (kofs + akc8) * 2);
                ldsm_x4(ah[fm], ahB + off);
                ldsm_x4(al[fm], alB + off);
            }
            uint32_t bh[2][4], bl[2][4];
#pragma unroll
            for (int bi = 0; bi < 2; bi++) {
                const uint32_t off =
                    (uint32_t)((wn * 32 + bi * 16 + brow) * PADB +
                               (kofs + bkc8) * 2);
                ldsm_x4(bh[bi], bhB + off);
                ldsm_x4(bl[bi], blB + off);
            }
#pragma unroll
            for (int fm = 0; fm < 4; fm++) {
#pragma unroll
                for (int fn = 0; fn < 4; fn++) {
                    const uint32_t* ph = &bh[fn >> 1][(fn & 1) * 2];
                    const uint32_t* pl = &bl[fn >> 1][(fn & 1) * 2];
                    mma16816(acc[fm][fn], ah[fm], ph);
                    mma16816(acc[fm][fn], ah[fm], pl);
                    mma16816(acc[fm][fn], al[fm], ph);
                }
            }
        }
        __syncthreads();
    }

    const int r0 = lane >> 2;
    const int c0 = (lane & 3) * 2;
#pragma unroll
    for (int fm = 0; fm < 4; fm++) {
#pragma unroll
        for (int fn = 0; fn < 4; fn++) {
            const size_t row = (size_t)(mBase + wm * 64 + fm * 16 + r0);
            const int col = nBase + wn * 32 + fn * 8 + c0;
            *(float2*)(C + row * N + col) =
                make_float2(acc[fm][fn][0], acc[fm][fn][1]);
            *(float2*)(C + (row + 8) * N + col) =
                make_float2(acc[fm][fn][2], acc[fm][fn][3]);
        }
    }
}

// ---------------------------------------------------------------------------
// Flash attention on tensor cores (mma.sync, hi/lo split, online softmax).
// CTA: 256 threads / 8 warps; q-tile 128 rows (16 per warp), key-tile 64.
// Q hi/lo resident in smem; K + V^T hi/lo double-buffered via cp.async.
// Smem rows padded (272B for 128-d rows, 144B for 64-key rows) so every
// ldmatrix phase is bank-conflict-free.
// ---------------------------------------------------------------------------
#define FQ_BYTES   (128 * 272)            // 34816 per Q matrix
#define FK_BYTES   (64 * 272)             // 17408 per K matrix
#define FV_BYTES   (128 * 144)            // 18432 per Vt matrix
#define FSTAGE     (2 * FK_BYTES + 2 * FV_BYTES)   // 71680
#define FQ_TOTAL   (2 * FQ_BYTES)                  // 69632
#define FA_SMEM    (FQ_TOTAL + 2 * FSTAGE)         // 212992

__global__ __launch_bounds__(256, 1) void flash_mma_kernel(
    const __nv_bfloat16* __restrict__ qh, const __nv_bfloat16* __restrict__ ql,
    const __nv_bfloat16* __restrict__ kh, const __nv_bfloat16* __restrict__ kl,
    const __nv_bfloat16* __restrict__ vth, const __nv_bfloat16* __restrict__ vtl,
    float* __restrict__ y)
{
    extern __shared__ char smc[];
    const uint32_t sbase = smem_u32(smc);
    const int tid = threadIdx.x;
    const int lane = tid & 31;
    const int wid = tid >> 5;
    const int b = blockIdx.z, h = blockIdx.y;
    const int bh = b * NH + h;
    const int q0 = blockIdx.x * 128;
    const size_t bT = (size_t)b * TT;
    const int hoff = h * HD;

    // ---- Q load (group 0) ----
    {
#pragma unroll
        for (int i = 0; i < 8; i++) {
            int cid = i * 256 + tid;
            int row = cid >> 4, ch = cid & 15;
            const __nv_bfloat16* sq = qh + (bT + q0 + row) * N_EMBD + hoff + ch * 8;
            const __nv_bfloat16* sl = ql + (bT + q0 + row) * N_EMBD + hoff + ch * 8;
            CP_ASYNC16(sbase + row * 272 + ch * 16, sq);
            CP_ASYNC16(sbase + FQ_BYTES + row * 272 + ch * 16, sl);
        }
        CP_COMMIT();
    }

    auto issue_stage = [&](int it, int buf) {
        const uint32_t st = sbase + FQ_TOTAL + buf * FSTAGE;
        const int n0 = it * 64;
#pragma unroll
        for (int i = 0; i < 4; i++) {
            int cid = i * 256 + tid;
            int row = cid >> 4, ch = cid & 15;
            const __nv_bfloat16* sh = kh + (bT + n0 + row) * N_EMBD + hoff + ch * 8;
            const __nv_bfloat16* sl = kl + (bT + n0 + row) * N_EMBD + hoff + ch * 8;
            CP_ASYNC16(st + row * 272 + ch * 16, sh);
            CP_ASYNC16(st + FK_BYTES + row * 272 + ch * 16, sl);
        }
#pragma unroll
        for (int i = 0; i < 4; i++) {
            int cid = i * 256 + tid;
            int row = cid >> 3, ch = cid & 7;
            const __nv_bfloat16* sh = vth + (size_t)(bh * HD + row) * TT + n0 + ch * 8;
            const __nv_bfloat16* sl = vtl + (size_t)(bh * HD + row) * TT + n0 + ch * 8;
            CP_ASYNC16(st + 2 * FK_BYTES + row * 144 + ch * 16, sh);
            CP_ASYNC16(st + 2 * FK_BYTES + FV_BYTES + row * 144 + ch * 16, sl);
        }
    };

    issue_stage(0, 0);
    CP_COMMIT();

    const int arow = (lane & 7) + ((lane >> 3) & 1) * 8;
    const int aoff = (lane >> 4) * 16;               // bytes
    const int brow = (lane & 7) + ((lane >> 4) & 1) * 8;
    const int boff = ((lane >> 3) & 1) * 16;         // bytes
    const int g = lane >> 2;
    const int tq = lane & 3;

    float O[16][4];
#pragma unroll
    for (int i = 0; i < 16; i++)
#pragma unroll
        for (int r = 0; r < 4; r++) O[i][r] = 0.0f;
    float ma = -INFINITY, mb = -INFINITY, la = 0.0f, lb = 0.0f;
    const float sc = 0.08838834764831845f;           // 1/sqrt(128)

    const int niter = TT / 64;                        // 32
    for (int c = 0; c < niter; c++) {
        const int buf = c & 1;
        if (c + 1 < niter) issue_stage(c + 1, (c + 1) & 1);
        CP_COMMIT();
        CP_WAIT1();
        __syncthreads();

        const uint32_t kb = sbase + FQ_TOTAL + buf * FSTAGE;

        // ---- S = Q @ K^T (hi/lo 3-term) ----
        float s[8][4];
#pragma unroll
        for (int j = 0; j < 8; j++)
#pragma unroll
            for (int r = 0; r < 4; r++) s[j][r] = 0.0f;

#pragma unroll
        for (int kk = 0; kk < 8; kk++) {
            uint32_t qf[4], qlf[4];
            const uint32_t qo = (wid * 16 + arow) * 272 + kk * 32 + aoff;
            ldsm_x4(qf, sbase + qo);
            ldsm_x4(qlf, sbase + FQ_BYTES + qo);
#pragma unroll
            for (int bi = 0; bi < 4; bi++) {
                uint32_t khf[4], klf[4];
                const uint32_t ko = (bi * 16 + brow) * 272 + kk * 32 + boff;
                ldsm_x4(khf, kb + ko);
                ldsm_x4(klf, kb + FK_BYTES + ko);
                mma16816(s[2 * bi],     qf,  khf);
                mma16816(s[2 * bi],     qf,  klf);
                mma16816(s[2 * bi],     qlf, khf);
                mma16816(s[2 * bi + 1], qf,  khf + 2);
                mma16816(s[2 * bi + 1], qf,  klf + 2);
                mma16816(s[2 * bi + 1], qlf, khf + 2);
            }
        }

        // ---- online softmax (rows g and g+8 per thread) ----
        float mxa = -INFINITY, mxb = -INFINITY;
#pragma unroll
        for (int j = 0; j < 8; j++) {
            s[j][0] *= sc; s[j][1] *= sc; s[j][2] *= sc; s[j][3] *= sc;
            mxa = fmaxf(mxa, fmaxf(s[j][0], s[j][1]));
            mxb = fmaxf(mxb, fmaxf(s[j][2], s[j][3]));
        }
        mxa = fmaxf(mxa, __shfl_xor_sync(0xffffffffu, mxa, 1));
        mxa = fmaxf(mxa, __shfl_xor_sync(0xffffffffu, mxa, 2));
        mxb = fmaxf(mxb, __shfl_xor_sync(0xffffffffu, mxb, 1));
        mxb = fmaxf(mxb, __shfl_xor_sync(0xffffffffu, mxb, 2));
        float mna = fmaxf(ma, mxa), mnb = fmaxf(mb, mxb);
        float alpha = __expf(ma - mna), beta = __expf(mb - mnb);
        ma = mna; mb = mnb;
        float sua = 0.0f, sub = 0.0f;
#pragma unroll
        for (int j = 0; j < 8; j++) {
            s[j][0] = __expf(s[j][0] - mna);
            s[j][1] = __expf(s[j][1] - mna);
            s[j][2] = __expf(s[j][2] - mnb);
            s[j][3] = __expf(s[j][3] - mnb);
            sua += s[j][0] + s[j][1];
            sub += s[j][2] + s[j][3];
        }
        sua += __shfl_xor_sync(0xffffffffu, sua, 1);
        sua += __shfl_xor_sync(0xffffffffu, sua, 2);
        sub += __shfl_xor_sync(0xffffffffu, sub, 1);
        sub += __shfl_xor_sync(0xffffffffu, sub, 2);
        la = la * alpha + sua;
        lb = lb * beta + sub;
#pragma unroll
        for (int j2 = 0; j2 < 16; j2++) {
            O[j2][0] *= alpha; O[j2][1] *= alpha;
            O[j2][2] *= beta;  O[j2][3] *= beta;
        }

        // ---- pack P to bf16 hi/lo A-fragments ----
        uint32_t Ph[4][4], Pl[4][4];
#pragma unroll
        for (int kp = 0; kp < 4; kp++) {
            pack_hl(s[2 * kp][0],     s[2 * kp][1],     Ph[kp][0], Pl[kp][0]);
            pack_hl(s[2 * kp][2],     s[2 * kp][3],     Ph[kp][1], Pl[kp][1]);
            pack_hl(s[2 * kp + 1][0], s[2 * kp + 1][1], Ph[kp][2], Pl[kp][2]);
            pack_hl(s[2 * kp + 1][2], s[2 * kp + 1][3], Ph[kp][3], Pl[kp][3]);
        }

        // ---- O += P @ V (V^T tiles, hi/lo 3-term) ----
        const uint32_t vb = kb + 2 * FK_BYTES;
#pragma unroll
        for (int kp = 0; kp < 4; kp++) {
#pragma unroll
            for (int j4 = 0; j4 < 8; j4++) {
                uint32_t vhf[4], vlf[4];
                const uint32_t vo = (j4 * 16 + brow) * 144 + kp * 32 + boff;
                ldsm_x4(vhf, vb + vo);
                ldsm_x4(vlf, vb + FV_BYTES + vo);
                mma16816(O[2 * j4],     Ph[kp], vhf);
                mma16816(O[2 * j4],     Ph[kp], vlf);
                mma16816(O[2 * j4],     Pl[kp], vhf);
                mma16816(O[2 * j4 + 1], Ph[kp], vhf + 2);
                mma16816(O[2 * j4 + 1], Ph[kp], vlf + 2);
                mma16816(O[2 * j4 + 1], Pl[kp], vhf + 2);
            }
        }
        __syncthreads();
    }

    // ---- epilogue ----
    const float inva = 1.0f / la, invb = 1.0f / lb;
    const size_t rowa = bT + q0 + wid * 16 + g;
    const size_t rowb = rowa + 8;
#pragma unroll
    for (int j2 = 0; j2 < 16; j2++) {
        const int col = hoff + j2 * 8 + tq * 2;
        *(float2*)(y + rowa * N_EMBD + col) =
            make_float2(O[j2][0] * inva, O[j2][1] * inva);
        *(float2*)(y + rowb * N_EMBD + col) =
            make_float2(O[j2][2] * invb, O[j2][3] * invb);
    }
}

// ---------------------------------------------------------------------------
// Launch
// ---------------------------------------------------------------------------
extern "C" void kernel_launch(void* const* d_in, const int* in_sizes, int n_in,
                              void* d_out, int out_size)
{
    const float* x      = (const float*)d_in[0];
    const float* w_attn = (const float*)d_in[1];
    const float* w_proj = (const float*)d_in[2];
    float* out = (float*)d_out;

    float *qkv = nullptr, *y = nullptr;
    __nv_bfloat16 *Ah, *Al, *Bh, *Bl, *Vth, *Vtl;
    cudaGetSymbolAddress((void**)&qkv, g_qkv);
    cudaGetSymbolAddress((void**)&y, g_y);
    cudaGetSymbolAddress((void**)&Ah, g_Ah);
    cudaGetSymbolAddress((void**)&Al, g_Al);
    cudaGetSymbolAddress((void**)&Bh, g_Bh);
    cudaGetSymbolAddress((void**)&Bl, g_Bl);
    cudaGetSymbolAddress((void**)&Vth, g_Vth);
    cudaGetSymbolAddress((void**)&Vtl, g_Vtl);

    cudaFuncSetAttribute(gemm_mma_kernel,
                         cudaFuncAttributeMaxDynamicSharedMemorySize, GEMM_SMEM);
    cudaFuncSetAttribute(flash_mma_kernel,
                         cudaFuncAttributeMaxDynamicSharedMemorySize, FA_SMEM);

    const int n4 = MROWS * N_EMBD / 4;

    // 1. RoPE table
    rope_table_kernel<<<(TT * 64 + 255) / 256, 256>>>();

    // 2. Split-convert x and w_attn^T
    conv_rm_kernel<<<(n4 + 255) / 256, 256>>>(x, Ah, Al, n4);
    conv_tr_kernel<<<dim3(QKV_N / 32, N_EMBD / 32), dim3(32, 8)>>>(
        w_attn, Bh, Bl, N_EMBD, QKV_N);

    // 3. QKV projection
    gemm_mma_kernel<<<dim3(QKV_N / BN, MROWS / BM), 256, GEMM_SMEM>>>(
        Ah, Al, Bh, Bl, qkv, MROWS, QKV_N, N_EMBD);

    // 4. RoPE + split q -> Ah/Al, k -> Bh/Bl; transpose-split v -> Vth/Vtl
    conv_rope_kernel<<<(MROWS * 512 + 255) / 256, 256>>>(qkv, 0, Ah, Al);
    conv_rope_kernel<<<(MROWS * 512 + 255) / 256, 256>>>(qkv, N_EMBD, Bh, Bl);
    conv_vt_kernel<<<dim3(TT / 32, HD / 32, BB * NH), dim3(32, 8)>>>(qkv, Vth, Vtl);

    // 5. Flash attention on tensor cores -> g_y
    flash_mma_kernel<<<dim3(TT / 128, NH, BB), 256, FA_SMEM>>>(
        Ah, Al, Bh, Bl, Vth, Vtl, y);

    // 6. Split-convert y and w_proj^T (reuse Ah/Al, Bh/Bl)
    conv_rm_kernel<<<(n4 + 255) / 256, 256>>>(y, Ah, Al, n4);
    conv_tr_kernel<<<dim3(N_EMBD / 32, N_EMBD / 32), dim3(32, 8)>>>(
        w_proj, Bh, Bl, N_EMBD, N_EMBD);

    // 7. Output projection
    gemm_mma_kernel<<<dim3(N_EMBD / BN, MROWS / BM), 256, GEMM_SMEM>>>(
        Ah, Al, Bh, Bl, out, MROWS, N_EMBD, N_EMBD);
}

// round 7
// speedup vs baseline: 2.9088x; 1.0348x over previous
#include <cuda_runtime.h>
#include <cuda_bf16.h>
#include <stdint.h>
#include <math.h>

// ---------------------------------------------------------------------------
// Problem constants
// ---------------------------------------------------------------------------
#define N_EMBD 2048
#define NH     16
#define HD     128
#define TT     2048         // seq len
#define BB     2            // batch
#define MROWS  (BB * TT)    // 4096 flattened (b, t) rows
#define QKV_N  (3 * N_EMBD) // 6144

// ---------------------------------------------------------------------------
// Scratch (no cudaMalloc allowed -> static __device__ globals)
// ---------------------------------------------------------------------------
__device__ float g_qkv[(size_t)MROWS * QKV_N];   // 100.7 MB
__device__ float g_y[(size_t)MROWS * N_EMBD];    //  33.6 MB
__device__ float g_cos[TT * (HD / 2)];
__device__ float g_sin[TT * (HD / 2)];
// bf16 hi/lo split operands (multi-purpose, reused across phases)
__device__ __nv_bfloat16 g_Ah[(size_t)MROWS * N_EMBD];   // x-split / q-split / y-split
__device__ __nv_bfloat16 g_Al[(size_t)MROWS * N_EMBD];
__device__ __nv_bfloat16 g_Bh[(size_t)QKV_N * N_EMBD];   // w_attn^T / k-split / w_proj^T
__device__ __nv_bfloat16 g_Bl[(size_t)QKV_N * N_EMBD];
__device__ __nv_bfloat16 g_Vth[(size_t)MROWS * N_EMBD];  // V^T per head [bh][d][t]
__device__ __nv_bfloat16 g_Vtl[(size_t)MROWS * N_EMBD];

// ---------------------------------------------------------------------------
// Helpers (plain sm_103-legal PTX only: ldmatrix / mma.sync / cp.async)
// ---------------------------------------------------------------------------
__device__ __forceinline__ uint32_t smem_u32(const void* p) {
    uint32_t a;
    asm("{ .reg .u64 t; cvta.to.shared.u64 t, %1; cvt.u32.u64 %0, t; }"
        : "=r"(a) : "l"(p));
    return a;
}

__device__ __forceinline__ void ldsm_x4(uint32_t* r, uint32_t addr) {
    asm volatile("ldmatrix.sync.aligned.m8n8.x4.shared.b16 {%0,%1,%2,%3}, [%4];"
                 : "=r"(r[0]), "=r"(r[1]), "=r"(r[2]), "=r"(r[3]) : "r"(addr));
}

__device__ __forceinline__ void mma16816(float* c, const uint32_t* a,
                                         const uint32_t* b) {
    asm volatile(
        "mma.sync.aligned.m16n8k16.row.col.f32.bf16.bf16.f32 "
        "{%0,%1,%2,%3}, {%4,%5,%6,%7}, {%8,%9}, {%0,%1,%2,%3};"
        : "+f"(c[0]), "+f"(c[1]), "+f"(c[2]), "+f"(c[3])
        : "r"(a[0]), "r"(a[1]), "r"(a[2]), "r"(a[3]), "r"(b[0]), "r"(b[1]));
}

#define CP_ASYNC16(dst, src) \
    asm volatile("cp.async.cg.shared.global [%0], [%1], 16;" \
                 :: "r"(dst), "l"(src) : "memory")
#define CP_COMMIT() asm volatile("cp.async.commit_group;" ::: "memory")
#define CP_WAIT1()  asm volatile("cp.async.wait_group 1;" ::: "memory")

__device__ __forceinline__ void split2(float x, __nv_bfloat16& h, __nv_bfloat16& l) {
    h = __float2bfloat16(x);
    l = __float2bfloat16(x - __bfloat162float(h));
}

// pack two floats into bf16x2 hi + residual bf16x2 lo
__device__ __forceinline__ void pack_hl(float x, float y, uint32_t& h, uint32_t& l) {
    __nv_bfloat162 hh = __floats2bfloat162_rn(x, y);
    float rx = x - __bfloat162float(hh.x);
    float ry = y - __bfloat162float(hh.y);
    __nv_bfloat162 ll = __floats2bfloat162_rn(rx, ry);
    h = *(uint32_t*)&hh;
    l = *(uint32_t*)&ll;
}

// ---------------------------------------------------------------------------
// Convert kernels
// ---------------------------------------------------------------------------
__global__ void conv_rm_kernel(const float* __restrict__ in,
                               __nv_bfloat16* __restrict__ oh,
                               __nv_bfloat16* __restrict__ ol, int n4) {
    int idx = blockIdx.x * blockDim.x + threadIdx.x;
    if (idx >= n4) return;
    float4 v = ((const float4*)in)[idx];
    __nv_bfloat16 h0, h1, h2, h3, l0, l1, l2, l3;
    split2(v.x, h0, l0); split2(v.y, h1, l1);
    split2(v.z, h2, l2); split2(v.w, h3, l3);
    ((__nv_bfloat162*)oh)[idx * 2]     = __halves2bfloat162(h0, h1);
    ((__nv_bfloat162*)oh)[idx * 2 + 1] = __halves2bfloat162(h2, h3);
    ((__nv_bfloat162*)ol)[idx * 2]     = __halves2bfloat162(l0, l1);
    ((__nv_bfloat162*)ol)[idx * 2 + 1] = __halves2bfloat162(l2, l3);
}

// B[K][N] fp32 row-major -> BT[N][K] bf16 hi/lo
__global__ void conv_tr_kernel(const float* __restrict__ B,
                               __nv_bfloat16* __restrict__ bh,
                               __nv_bfloat16* __restrict__ bl, int K, int N) {
    __shared__ float tile[32][33];
    int n0 = blockIdx.x * 32, k0 = blockIdx.y * 32;
    int tx = threadIdx.x, ty = threadIdx.y;
#pragma unroll
    for (int i = 0; i < 4; i++)
        tile[ty + i * 8][tx] = B[(size_t)(k0 + ty + i * 8) * N + n0 + tx];
    __syncthreads();
#pragma unroll
    for (int i = 0; i < 4; i++) {
        int n = ty + i * 8;
        float v = tile[tx][n];
        __nv_bfloat16 h, l;
        split2(v, h, l);
        size_t o = (size_t)(n0 + n) * K + k0 + tx;
        bh[o] = h;
        bl[o] = l;
    }
}

// q or k section of g_qkv: apply RoPE + split to bf16 hi/lo [m][2048]
__global__ void conv_rope_kernel(const float* __restrict__ qkv, int secOff,
                                 __nv_bfloat16* __restrict__ oh,
                                 __nv_bfloat16* __restrict__ ol) {
    int idx = blockIdx.x * blockDim.x + threadIdx.x;
    if (idx >= MROWS * 512) return;
    int m = idx >> 9;
    int col = (idx & 511) * 4;
    int t = m & (TT - 1);
    int i0 = (col & 127) >> 1;
    float4 v = *(const float4*)(qkv + (size_t)m * QKV_N + secOff + col);
    float c0 = g_cos[t * 64 + i0],     s0 = g_sin[t * 64 + i0];
    float c1 = g_cos[t * 64 + i0 + 1], s1 = g_sin[t * 64 + i0 + 1];
    float r0 = v.x * c0 - v.y * s0;
    float r1 = v.y * c0 + v.x * s0;
    float r2 = v.z * c1 - v.w * s1;
    float r3 = v.w * c1 + v.z * s1;
    __nv_bfloat16 h0, h1, h2, h3, l0, l1, l2, l3;
    split2(r0, h0, l0); split2(r1, h1, l1);
    split2(r2, h2, l2); split2(r3, h3, l3);
    size_t o = (size_t)m * N_EMBD + col;
    *(__nv_bfloat162*)(oh + o)     = __halves2bfloat162(h0, h1);
    *(__nv_bfloat162*)(oh + o + 2) = __halves2bfloat162(h2, h3);
    *(__nv_bfloat162*)(ol + o)     = __halves2bfloat162(l0, l1);
    *(__nv_bfloat162*)(ol + o + 2) = __halves2bfloat162(l2, l3);
}

// V section of g_qkv -> per-head transposed bf16 hi/lo: vt[(bh*128+d)*2048 + t]
__global__ void conv_vt_kernel(const float* __restrict__ qkv,
                               __nv_bfloat16* __restrict__ vh,
                               __nv_bfloat16* __restrict__ vl) {
    __shared__ float tile[32][33];
    int bh = blockIdx.z;
    int b = bh >> 4, h = bh & 15;
    int t0 = blockIdx.x * 32, d0 = blockIdx.y * 32;
    int tx = threadIdx.x, ty = threadIdx.y;
#pragma unroll
    for (int i = 0; i < 4; i++)
        tile[ty + i * 8][tx] =
            qkv[(size_t)(b * TT + t0 + ty + i * 8) * QKV_N + 2 * N_EMBD + h * HD + d0 + tx];
    __syncthreads();
#pragma unroll
    for (int i = 0; i < 4; i++) {
        int d = ty + i * 8;
        float v = tile[tx][d];
        __nv_bfloat16 hh, ll;
        split2(v, hh, ll);
        size_t o = (size_t)(bh * HD + d0 + d) * TT + t0 + tx;
        vh[o] = hh;
        vl[o] = ll;
    }
}

// ---------------------------------------------------------------------------
// RoPE table
// ---------------------------------------------------------------------------
__global__ void rope_table_kernel() {
    int idx = blockIdx.x * blockDim.x + threadIdx.x;
    if (idx >= TT * 64) return;
    int t = idx >> 6;
    int i = idx & 63;
    double theta = pow(10000.0, -(double)i / 64.0);
    double ang = (double)t * theta;
    g_cos[idx] = (float)cos(ang);
    g_sin[idx] = (float)sin(ang);
}

// ---------------------------------------------------------------------------
// Tensor-core GEMM via mma.sync. CTA tile 128x256, BK=32, 8 warps, each
// warp computes 64x64 (4 m-frags x 8 n-frags). MMA:ldsm ratio 6:1.
// ---------------------------------------------------------------------------
#define BM 128
#define BN 256
#define BK 32
#define PADB 80                        // padded row stride in bytes (40 bf16)
#define A_BYTES (128 * PADB)           // 10240 per A matrix (hi or lo)
#define B_BYTES (256 * PADB)           // 20480 per B matrix (hi or lo)
#define STG_BYTES (2 * A_BYTES + 2 * B_BYTES)   // 61440
#define GEMM_SMEM (2 * STG_BYTES)               // 122880

__global__ __launch_bounds__(256, 1) void gemm_mma_kernel(
    const __nv_bfloat16* __restrict__ Ah, const __nv_bfloat16* __restrict__ Al,
    const __nv_bfloat16* __restrict__ Bh, const __nv_bfloat16* __restrict__ Bl,
    float* __restrict__ C, int M, int N, int K)
{
    extern __shared__ char smc[];
    const uint32_t sbase = smem_u32(smc);
    const int tid = threadIdx.x;
    const int lane = tid & 31;
    const int wid = tid >> 5;
    const int wm = wid & 1;            // 2 warps in M (64 each)
    const int wn = wid >> 1;           // 4 warps in N (64 each)
    const int mBase = blockIdx.y * BM;
    const int nBase = blockIdx.x * BN;
    const int nch = K / BK;

    const int ldRow = tid >> 2;        // 0..63
    const int ldCh  = tid & 3;         // 16B chunk within 64B of K-row

    float acc[4][8][4];
#pragma unroll
    for (int i = 0; i < 4; i++)
#pragma unroll
        for (int j = 0; j < 8; j++)
#pragma unroll
            for (int r = 0; r < 4; r++) acc[i][j][r] = 0.0f;

    // stage loader: 12 x 16B cp.async per thread
    auto issue_stage = [&](int c, int buf) {
        const uint32_t st = sbase + buf * STG_BYTES;
        const int kOff = c * BK;
#pragma unroll
        for (int i = 0; i < 2; i++) {          // A rows 0..127
            const int row = i * 64 + ldRow;
            const uint32_t so = row * PADB + ldCh * 16;
            CP_ASYNC16(st + so,
                       Ah + (size_t)(mBase + row) * K + kOff + ldCh * 8);
            CP_ASYNC16(st + A_BYTES + so,
                       Al + (size_t)(mBase + row) * K + kOff + ldCh * 8);
        }
#pragma unroll
        for (int i = 0; i < 4; i++) {          // B rows 0..255
            const int row = i * 64 + ldRow;
            const uint32_t so = row * PADB + ldCh * 16;
            CP_ASYNC16(st + 2 * A_BYTES + so,
                       Bh + (size_t)(nBase + row) * K + kOff + ldCh * 8);
            CP_ASYNC16(st + 2 * A_BYTES + B_BYTES + so,
                       Bl + (size_t)(nBase + row) * K + kOff + ldCh * 8);
        }
    };

    issue_stage(0, 0);
    CP_COMMIT();

    const int arow = (lane & 7) + ((lane >> 3) & 1) * 8;
    const int akc8 = (lane >> 4) * 8;
    const int brow = (lane & 7) + ((lane >> 4) & 1) * 8;
    const int bkc8 = ((lane >> 3) & 1) * 8;

    for (int c = 0; c < nch; c++) {
        const int buf = c & 1;
        if (c + 1 < nch) issue_stage(c + 1, (c + 1) & 1);
        CP_COMMIT();
        CP_WAIT1();
        __syncthreads();

        const uint32_t st = sbase + buf * STG_BYTES;
        const uint32_t ahB = st;
        const uint32_t alB = st + A_BYTES;
        const uint32_t bhB = st + 2 * A_BYTES;
        const uint32_t blB = st + 2 * A_BYTES + B_BYTES;

#pragma unroll
        for (int s = 0; s < 2; s++) {
            const int kofs = s * 16;
            uint32_t ah[4][4], al[4][4];
#pragma unroll
            for (int fm = 0; fm < 4; fm++) {
                const uint32_t off =
                    (uint32_t)((wm * 64 + fm * 16 + arow) * PADB +
                               (kofs + akc8) * 2);
                ldsm_x4(ah[fm], ahB + off);
                ldsm_x4(al[fm], alB + off);
            }
#pragma unroll
            for (int bi = 0; bi < 4; bi++) {
                uint32_t bh[4], bl[4];
                const uint32_t off =
                    (uint32_t)((wn * 64 + bi * 16 + brow) * PADB +
                               (kofs + bkc8) * 2);
                ldsm_x4(bh, bhB + off);
                ldsm_x4(bl, blB + off);
#pragma unroll
                for (int fm = 0; fm < 4; fm++) {
                    mma16816(acc[fm][2 * bi],     ah[fm], bh);
                    mma16816(acc[fm][2 * bi],     ah[fm], bl);
                    mma16816(acc[fm][2 * bi],     al[fm], bh);
                    mma16816(acc[fm][2 * bi + 1], ah[fm], bh + 2);
                    mma16816(acc[fm][2 * bi + 1], ah[fm], bl + 2);
                    mma16816(acc[fm][2 * bi + 1], al[fm], bh + 2);
                }
            }
        }
        __syncthreads();
    }

    // Epilogue: direct float2 stores
    const int r0 = lane >> 2;
    const int c0 = (lane & 3) * 2;
#pragma unroll
    for (int fm = 0; fm < 4; fm++) {
#pragma unroll
        for (int fn = 0; fn < 8; fn++) {
            const size_t row = (size_t)(mBase + wm * 64 + fm * 16 + r0);
            const int col = nBase + wn * 64 + fn * 8 + c0;
            *(float2*)(C + row * N + col) =
                make_float2(acc[fm][fn][0], acc[fm][fn][1]);
            *(float2*)(C + (row + 8) * N + col) =
                make_float2(acc[fm][fn][2], acc[fm][fn][3]);
        }
    }
}

// ---------------------------------------------------------------------------
// Flash attention on tensor cores (mma.sync, hi/lo split, online softmax).
// Unchanged from R5 (passed at ~550us).
// ---------------------------------------------------------------------------
#define FQ_BYTES   (128 * 272)
#define FK_BYTES   (64 * 272)
#define FV_BYTES   (128 * 144)
#define FSTAGE     (2 * FK_BYTES + 2 * FV_BYTES)
#define FQ_TOTAL   (2 * FQ_BYTES)
#define FA_SMEM    (FQ_TOTAL + 2 * FSTAGE)

__global__ __launch_bounds__(256, 1) void flash_mma_kernel(
    const __nv_bfloat16* __restrict__ qh, const __nv_bfloat16* __restrict__ ql,
    const __nv_bfloat16* __restrict__ kh, const __nv_bfloat16* __restrict__ kl,
    const __nv_bfloat16* __restrict__ vth, const __nv_bfloat16* __restrict__ vtl,
    float* __restrict__ y)
{
    extern __shared__ char smc[];
    const uint32_t sbase = smem_u32(smc);
    const int tid = threadIdx.x;
    const int lane = tid & 31;
    const int wid = tid >> 5;
    const int b = blockIdx.z, h = blockIdx.y;
    const int bh = b * NH + h;
    const int q0 = blockIdx.x * 128;
    const size_t bT = (size_t)b * TT;
    const int hoff = h * HD;

    {
#pragma unroll
        for (int i = 0; i < 8; i++) {
            int cid = i * 256 + tid;
            int row = cid >> 4, ch = cid & 15;
            const __nv_bfloat16* sq = qh + (bT + q0 + row) * N_EMBD + hoff + ch * 8;
            const __nv_bfloat16* sl = ql + (bT + q0 + row) * N_EMBD + hoff + ch * 8;
            CP_ASYNC16(sbase + row * 272 + ch * 16, sq);
            CP_ASYNC16(sbase + FQ_BYTES + row * 272 + ch * 16, sl);
        }
        CP_COMMIT();
    }

    auto issue_stage = [&](int it, int buf) {
        const uint32_t st = sbase + FQ_TOTAL + buf * FSTAGE;
        const int n0 = it * 64;
#pragma unroll
        for (int i = 0; i < 4; i++) {
            int cid = i * 256 + tid;
            int row = cid >> 4, ch = cid & 15;
            const __nv_bfloat16* sh = kh + (bT + n0 + row) * N_EMBD + hoff + ch * 8;
            const __nv_bfloat16* sl = kl + (bT + n0 + row) * N_EMBD + hoff + ch * 8;
            CP_ASYNC16(st + row * 272 + ch * 16, sh);
            CP_ASYNC16(st + FK_BYTES + row * 272 + ch * 16, sl);
        }
#pragma unroll
        for (int i = 0; i < 4; i++) {
            int cid = i * 256 + tid;
            int row = cid >> 3, ch = cid & 7;
            const __nv_bfloat16* sh = vth + (size_t)(bh * HD + row) * TT + n0 + ch * 8;
            const __nv_bfloat16* sl = vtl + (size_t)(bh * HD + row) * TT + n0 + ch * 8;
            CP_ASYNC16(st + 2 * FK_BYTES + row * 144 + ch * 16, sh);
            CP_ASYNC16(st + 2 * FK_BYTES + FV_BYTES + row * 144 + ch * 16, sl);
        }
    };

    issue_stage(0, 0);
    CP_COMMIT();

    const int arow = (lane & 7) + ((lane >> 3) & 1) * 8;
    const int aoff = (lane >> 4) * 16;
    const int brow = (lane & 7) + ((lane >> 4) & 1) * 8;
    const int boff = ((lane >> 3) & 1) * 16;
    const int g = lane >> 2;
    const int tq = lane & 3;

    float O[16][4];
#pragma unroll
    for (int i = 0; i < 16; i++)
#pragma unroll
        for (int r = 0; r < 4; r++) O[i][r] = 0.0f;
    float ma = -INFINITY, mb = -INFINITY, la = 0.0f, lb = 0.0f;
    const float sc = 0.08838834764831845f;

    const int niter = TT / 64;
    for (int c = 0; c < niter; c++) {
        const int buf = c & 1;
        if (c + 1 < niter) issue_stage(c + 1, (c + 1) & 1);
        CP_COMMIT();
        CP_WAIT1();
        __syncthreads();

        const uint32_t kb = sbase + FQ_TOTAL + buf * FSTAGE;

        float s[8][4];
#pragma unroll
        for (int j = 0; j < 8; j++)
#pragma unroll
            for (int r = 0; r < 4; r++) s[j][r] = 0.0f;

#pragma unroll
        for (int kk = 0; kk < 8; kk++) {
            uint32_t qf[4], qlf[4];
            const uint32_t qo = (wid * 16 + arow) * 272 + kk * 32 + aoff;
            ldsm_x4(qf, sbase + qo);
            ldsm_x4(qlf, sbase + FQ_BYTES + qo);
#pragma unroll
            for (int bi = 0; bi < 4; bi++) {
                uint32_t khf[4], klf[4];
                const uint32_t ko = (bi * 16 + brow) * 272 + kk * 32 + boff;
                ldsm_x4(khf, kb + ko);
                ldsm_x4(klf, kb + FK_BYTES + ko);
                mma16816(s[2 * bi],     qf,  khf);
                mma16816(s[2 * bi],     qf,  klf);
                mma16816(s[2 * bi],     qlf, khf);
                mma16816(s[2 * bi + 1], qf,  khf + 2);
                mma16816(s[2 * bi + 1], qf,  klf + 2);
                mma16816(s[2 * bi + 1], qlf, khf + 2);
            }
        }

        float mxa = -INFINITY, mxb = -INFINITY;
#pragma unroll
        for (int j = 0; j < 8; j++) {
            s[j][0] *= sc; s[j][1] *= sc; s[j][2] *= sc; s[j][3] *= sc;
            mxa = fmaxf(mxa, fmaxf(s[j][0], s[j][1]));
            mxb = fmaxf(mxb, fmaxf(s[j][2], s[j][3]));
        }
        mxa = fmaxf(mxa, __shfl_xor_sync(0xffffffffu, mxa, 1));
        mxa = fmaxf(mxa, __shfl_xor_sync(0xffffffffu, mxa, 2));
        mxb = fmaxf(mxb, __shfl_xor_sync(0xffffffffu, mxb, 1));
        mxb = fmaxf(mxb, __shfl_xor_sync(0xffffffffu, mxb, 2));
        float mna = fmaxf(ma, mxa), mnb = fmaxf(mb, mxb);
        float alpha = __expf(ma - mna), beta = __expf(mb - mnb);
        ma = mna; mb = mnb;
        float sua = 0.0f, sub = 0.0f;
#pragma unroll
        for (int j = 0; j < 8; j++) {
            s[j][0] = __expf(s[j][0] - mna);
            s[j][1] = __expf(s[j][1] - mna);
            s[j][2] = __expf(s[j][2] - mnb);
            s[j][3] = __expf(s[j][3] - mnb);
            sua += s[j][0] + s[j][1];
            sub += s[j][2] + s[j][3];
        }
        sua += __shfl_xor_sync(0xffffffffu, sua, 1);
        sua += __shfl_xor_sync(0xffffffffu, sua, 2);
        sub += __shfl_xor_sync(0xffffffffu, sub, 1);
        sub += __shfl_xor_sync(0xffffffffu, sub, 2);
        la = la * alpha + sua;
        lb = lb * beta + sub;
#pragma unroll
        for (int j2 = 0; j2 < 16; j2++) {
            O[j2][0] *= alpha; O[j2][1] *= alpha;
            O[j2][2] *= beta;  O[j2][3] *= beta;
        }

        uint32_t Ph[4][4], Pl[4][4];
#pragma unroll
        for (int kp = 0; kp < 4; kp++) {
            pack_hl(s[2 * kp][0],     s[2 * kp][1],     Ph[kp][0], Pl[kp][0]);
            pack_hl(s[2 * kp][2],     s[2 * kp][3],     Ph[kp][1], Pl[kp][1]);
            pack_hl(s[2 * kp + 1][0], s[2 * kp + 1][1], Ph[kp][2], Pl[kp][2]);
            pack_hl(s[2 * kp + 1][2], s[2 * kp + 1][3], Ph[kp][3], Pl[kp][3]);
        }

        const uint32_t vb = kb + 2 * FK_BYTES;
#pragma unroll
        for (int kp = 0; kp < 4; kp++) {
#pragma unroll
            for (int j4 = 0; j4 < 8; j4++) {
                uint32_t vhf[4], vlf[4];
                const uint32_t vo = (j4 * 16 + brow) * 144 + kp * 32 + boff;
                ldsm_x4(vhf, vb + vo);
                ldsm_x4(vlf, vb + FV_BYTES + vo);
                mma16816(O[2 * j4],     Ph[kp], vhf);
                mma16816(O[2 * j4],     Ph[kp], vlf);
                mma16816(O[2 * j4],     Pl[kp], vhf);
                mma16816(O[2 * j4 + 1], Ph[kp], vhf + 2);
                mma16816(O[2 * j4 + 1], Ph[kp], vlf + 2);
                mma16816(O[2 * j4 + 1], Pl[kp], vhf + 2);
            }
        }
        __syncthreads();
    }

    const float inva = 1.0f / la, invb = 1.0f / lb;
    const size_t rowa = bT + q0 + wid * 16 + g;
    const size_t rowb = rowa + 8;
#pragma unroll
    for (int j2 = 0; j2 < 16; j2++) {
        const int col = hoff + j2 * 8 + tq * 2;
        *(float2*)(y + rowa * N_EMBD + col) =
            make_float2(O[j2][0] * inva, O[j2][1] * inva);
        *(float2*)(y + rowb * N_EMBD + col) =
            make_float2(O[j2][2] * invb, O[j2][3] * invb);
    }
}

// ---------------------------------------------------------------------------
// Launch
// ---------------------------------------------------------------------------
extern "C" void kernel_launch(void* const* d_in, const int* in_sizes, int n_in,
                              void* d_out, int out_size)
{
    const float* x      = (const float*)d_in[0];
    const float* w_attn = (const float*)d_in[1];
    const float* w_proj = (const float*)d_in[2];
    float* out = (float*)d_out;

    float *qkv = nullptr, *y = nullptr;
    __nv_bfloat16 *Ah, *Al, *Bh, *Bl, *Vth, *Vtl;
    cudaGetSymbolAddress((void**)&qkv, g_qkv);
    cudaGetSymbolAddress((void**)&y, g_y);
    cudaGetSymbolAddress((void**)&Ah, g_Ah);
    cudaGetSymbolAddress((void**)&Al, g_Al);
    cudaGetSymbolAddress((void**)&Bh, g_Bh);
    cudaGetSymbolAddress((void**)&Bl, g_Bl);
    cudaGetSymbolAddress((void**)&Vth, g_Vth);
    cudaGetSymbolAddress((void**)&Vtl, g_Vtl);

    cudaFuncSetAttribute(gemm_mma_kernel,
                         cudaFuncAttributeMaxDynamicSharedMemorySize, GEMM_SMEM);
    cudaFuncSetAttribute(flash_mma_kernel,
                         cudaFuncAttributeMaxDynamicSharedMemorySize, FA_SMEM);

    const int n4 = MROWS * N_EMBD / 4;

    // 1. RoPE table
    rope_table_kernel<<<(TT * 64 + 255) / 256, 256>>>();

    // 2. Split-convert x and w_attn^T
    conv_rm_kernel<<<(n4 + 255) / 256, 256>>>(x, Ah, Al, n4);
    conv_tr_kernel<<<dim3(QKV_N / 32, N_EMBD / 32), dim3(32, 8)>>>(
        w_attn, Bh, Bl, N_EMBD, QKV_N);

    // 3. QKV projection
    gemm_mma_kernel<<<dim3(QKV_N / BN, MROWS / BM), 256, GEMM_SMEM>>>(
        Ah, Al, Bh, Bl, qkv, MROWS, QKV_N, N_EMBD);

    // 4. RoPE + split q -> Ah/Al, k -> Bh/Bl; transpose-split v -> Vth/Vtl
    conv_rope_kernel<<<(MROWS * 512 + 255) / 256, 256>>>(qkv, 0, Ah, Al);
    conv_rope_kernel<<<(MROWS * 512 + 255) / 256, 256>>>(qkv, N_EMBD, Bh, Bl);
    conv_vt_kernel<<<dim3(TT / 32, HD / 32, BB * NH), dim3(32, 8)>>>(qkv, Vth, Vtl);

    // 5. Flash attention on tensor cores -> g_y
    flash_mma_kernel<<<dim3(TT / 128, NH, BB), 256, FA_SMEM>>>(
        Ah, Al, Bh, Bl, Vth, Vtl, y);

    // 6. Split-convert y and w_proj^T (reuse Ah/Al, Bh/Bl)
    conv_rm_kernel<<<(n4 + 255) / 256, 256>>>(y, Ah, Al, n4);
    conv_tr_kernel<<<dim3(N_EMBD / 32, N_EMBD / 32), dim3(32, 8)>>>(
        w_proj, Bh, Bl, N_EMBD, N_EMBD);

    // 7. Output projection
    gemm_mma_kernel<<<dim3(N_EMBD / BN, MROWS / BM), 256, GEMM_SMEM>>>(
        Ah, Al, Bh, Bl, out, MROWS, N_EMBD, N_EMBD);
}